// round 17
// baseline (speedup 1.0000x reference)
#include <cuda_runtime.h>
#include <cuda_bf16.h>
#include <cuda_fp16.h>
#include <math.h>
#include <cstdint>

#define Gg   256
#define Nn   512
#define Ee   4096
#define FIN  64
#define FOUT 64
#define Cc   16
#define NK   (Nn * FOUT)          // 32768 flat features per graph
#define CSRE (Ee + Nn)            // 4608 CSR entries per graph
#define KS   16                   // k3 ksplit blocks
#define GT   16                   // k3 graph tiles (16 graphs each)

// ---------------- scratch ----------------
__device__ __half g_h16[(size_t)Gg * NK];          // relu(agg+bias) (fp16)
__device__ __half g_lwh[(size_t)Cc * NK];          // lin_weight fp16
__device__ float  g_logits[(size_t)Gg * Cc];
__device__ int    g_cnt[GT];

// ===========================================================================
// MMA macros (baseline PTX, valid at compute_103)
// ===========================================================================
#define MMA_BF16(d, a0, a1, a2, a3, b0, b1)                                 \
    asm volatile("mma.sync.aligned.m16n8k16.row.col.f32.bf16.bf16.f32 "     \
        "{%0,%1,%2,%3}, {%4,%5,%6,%7}, {%8,%9}, {%0,%1,%2,%3};"             \
        : "+f"((d)[0]), "+f"((d)[1]), "+f"((d)[2]), "+f"((d)[3])            \
        : "r"(a0), "r"(a1), "r"(a2), "r"(a3), "r"(b0), "r"(b1))

#define MMA_F16(d, a0, a1, a2, a3, b0, b1)                                  \
    asm volatile("mma.sync.aligned.m16n8k16.row.col.f32.f16.f16.f32 "       \
        "{%0,%1,%2,%3}, {%4,%5,%6,%7}, {%8,%9}, {%0,%1,%2,%3};"             \
        : "+f"((d)[0]), "+f"((d)[1]), "+f"((d)[2]), "+f"((d)[3])            \
        : "r"(a0), "r"(a1), "r"(a2), "r"(a3), "r"(b0), "r"(b1))

// pack two f32 -> bf16x2 in ONE op
__device__ __forceinline__ uint32_t cvt2bf(float vhi, float vlo)
{
    uint32_t r;
    asm("cvt.rn.bf16x2.f32 %0, %1, %2;" : "=r"(r) : "f"(vhi), "f"(vlo));
    return r;
}

// ===========================================================================
// kAB: ONE BLOCK PER GRAPH (512 thr, 2 blocks/SM, single wave).
//   Phase 1: GEMM xw = x[g] @ W^T (bf16 mma.sync) -> fp16 smem tile (pitch 33)
//   Phase 2: CSR build in smem (srow packed u16)
//   Phase 3: aggregate + bias + ReLU -> g_h16  (all gathers hit LDS)
//   Also converts its lw slice to fp16. No g_xw global round-trip.
// ===========================================================================
#define XSP  33                   // xs pitch in half2 (conflict-free st + ld)
#define OFF_XS    0
#define OFF_SROW  67584
#define OFF_SNORM 76800
#define OFF_CNT   95232
#define OFF_DV    97280
#define OFF_WCUR  99328
#define OFF_OFFX  101376
#define OFF_WB    103440
#define KAB_SMEM  112656

__global__ __launch_bounds__(512, 2) void kAB(const float* __restrict__ x,
                                              const float* __restrict__ w,
                                              const int*   __restrict__ ei,
                                              const float* __restrict__ lw,
                                              const float* __restrict__ conv_bias)
{
    extern __shared__ __align__(16) char sm[];
    __half2*  xs    = (__half2*) (sm + OFF_XS);     // [512][33] half2
    uint16_t* srow  = (uint16_t*)(sm + OFF_SROW);   // [CSRE]
    float*    snorm = (float*)   (sm + OFF_SNORM);  // [CSRE]
    int*      cnt   = (int*)     (sm + OFF_CNT);    // [512]
    float*    dv    = (float*)   (sm + OFF_DV);     // [512]
    int*      wcur  = (int*)     (sm + OFF_WCUR);   // [512]
    int*      offx  = (int*)     (sm + OFF_OFFX);   // [513]
    __nv_bfloat16 (*Wb)[72] = (__nv_bfloat16(*)[72])(sm + OFF_WB);

    const int g    = blockIdx.x;
    const int tid  = threadIdx.x;
    const int wid  = tid >> 5;
    const int lane = tid & 31;
    const int gq   = lane >> 2;
    const int t    = lane & 3;

    // ---- lw -> fp16, slice per block (256 blocks x 2048 = full 524288) ----
    {
        const size_t base = (size_t)g * 2048;
        for (int i = tid; i < 2048; i += 512)
            g_lwh[base + i] = __float2half_rn(lw[base + i]);
    }
    if (tid < Cc) g_logits[(size_t)g * Cc + tid] = 0.f;
    if (g < GT && tid == 0) g_cnt[g] = 0;

    // ---- Wb -> smem bf16 ----
    for (int i = tid; i < FOUT * FIN; i += 512) {
        int o = i >> 6, k = i & 63;
        Wb[o][k] = __float2bfloat16_rn(w[i]);
    }
    __syncthreads();

    // ---- Phase 1: GEMM. Warp = 32 rows (2 subtiles of 16). ----
    const float* xg = x + (size_t)g * Nn * FIN;

    #pragma unroll
    for (int s = 0; s < 2; s++) {
        const int row0 = wid * 32 + s * 16 + gq;

        float acc[8][4];
        #pragma unroll
        for (int nt = 0; nt < 8; nt++)
            #pragma unroll
            for (int i = 0; i < 4; i++) acc[nt][i] = 0.f;

        #pragma unroll
        for (int c = 0; c < 4; c++) {
            const int kb = c * 16;
            float2 v00 = __ldg((const float2*)&xg[(size_t)(row0    ) * FIN + kb +     2 * t]);
            float2 v10 = __ldg((const float2*)&xg[(size_t)(row0 + 8) * FIN + kb +     2 * t]);
            float2 v01 = __ldg((const float2*)&xg[(size_t)(row0    ) * FIN + kb + 8 + 2 * t]);
            float2 v11 = __ldg((const float2*)&xg[(size_t)(row0 + 8) * FIN + kb + 8 + 2 * t]);
            uint32_t a0 = cvt2bf(v00.y, v00.x);
            uint32_t a1 = cvt2bf(v10.y, v10.x);
            uint32_t a2 = cvt2bf(v01.y, v01.x);
            uint32_t a3 = cvt2bf(v11.y, v11.x);

            #pragma unroll
            for (int nt = 0; nt < 8; nt++) {
                const int n = nt * 8 + gq;
                uint32_t b0 = *(const uint32_t*)&Wb[n][kb +     2 * t];
                uint32_t b1 = *(const uint32_t*)&Wb[n][kb + 8 + 2 * t];
                MMA_BF16(acc[nt], a0, a1, a2, a3, b0, b1);
            }
        }

        // epilogue -> fp16 smem tile (pitch 33: row term gives distinct banks)
        #pragma unroll
        for (int nt = 0; nt < 8; nt++) {
            const int c2 = (nt * 8 + 2 * t) >> 1;
            xs[(row0    ) * XSP + c2] = __floats2half2_rn(acc[nt][0], acc[nt][1]);
            xs[(row0 + 8) * XSP + c2] = __floats2half2_rn(acc[nt][2], acc[nt][3]);
        }
    }

    // ---- Phase 2: CSR build ----
    const int* rowp = ei + (size_t)g * 2 * Ee;
    const int* colp = rowp + Ee;

    cnt[tid] = 1;                          // self-loop
    __syncthreads();
    for (int e = tid; e < Ee; e += 512)
        atomicAdd(&cnt[colp[e]], 1);
    __syncthreads();

    const int myc = cnt[tid];
    dv[tid]   = rsqrtf((float)myc);
    wcur[tid] = myc;                       // scan buffer
    __syncthreads();

    for (int s = 1; s < Nn; s <<= 1) {
        int v = (tid >= s) ? wcur[tid - s] : 0;
        __syncthreads();
        wcur[tid] += v;
        __syncthreads();
    }
    const int incl = wcur[tid];
    const int excl = incl - myc;
    offx[tid + 1] = incl;
    if (tid == 0) offx[0] = 0;
    srow[excl]  = (uint16_t)tid;           // self-loop entry first
    snorm[excl] = dv[tid] * dv[tid];
    cnt[tid] = excl + 1;                   // write cursor
    __syncthreads();

    for (int e = tid; e < Ee; e += 512) {
        int r = rowp[e], c = colp[e];
        int pos = atomicAdd(&cnt[c], 1);
        srow[pos]  = (uint16_t)r;
        snorm[pos] = dv[r] * dv[c];
    }
    __syncthreads();

    // ---- Phase 3: aggregate (warp-per-node, gathers in LDS) ----
    __half2* h2 = (__half2*)(g_h16 + (size_t)g * NK);
    const float bx0 = __ldg(&conv_bias[lane * 2]);
    const float bx1 = __ldg(&conv_bias[lane * 2 + 1]);

    for (int n = wid; n < Nn; n += 16) {
        const int b  = offx[n];
        const int e2 = offx[n + 1];

        float a0x = 0.f, a0y = 0.f, a1x = 0.f, a1y = 0.f;
        float a2x = 0.f, a2y = 0.f, a3x = 0.f, a3y = 0.f;
        int j = b;
        for (; j + 4 <= e2; j += 4) {
            int   r0 = srow[j],   r1 = srow[j+1], r2 = srow[j+2], r3 = srow[j+3];
            float m0 = snorm[j],  m1 = snorm[j+1], m2 = snorm[j+2], m3 = snorm[j+3];
            float2 v0 = __half22float2(xs[r0 * XSP + lane]);
            float2 v1 = __half22float2(xs[r1 * XSP + lane]);
            float2 v2 = __half22float2(xs[r2 * XSP + lane]);
            float2 v3 = __half22float2(xs[r3 * XSP + lane]);
            a0x = fmaf(v0.x, m0, a0x);  a0y = fmaf(v0.y, m0, a0y);
            a1x = fmaf(v1.x, m1, a1x);  a1y = fmaf(v1.y, m1, a1y);
            a2x = fmaf(v2.x, m2, a2x);  a2y = fmaf(v2.y, m2, a2y);
            a3x = fmaf(v3.x, m3, a3x);  a3y = fmaf(v3.y, m3, a3y);
        }
        for (; j < e2; j++) {
            int   r  = srow[j];
            float nm = snorm[j];
            float2 v = __half22float2(xs[r * XSP + lane]);
            a0x = fmaf(v.x, nm, a0x);  a0y = fmaf(v.y, nm, a0y);
        }
        float ax = (a0x + a1x) + (a2x + a3x);
        float ay = (a0y + a1y) + (a2y + a3y);
        ax = fmaxf(ax + bx0, 0.f);
        ay = fmaxf(ay + bx1, 0.f);
        h2[n * 32 + lane] = __floats2half2_rn(ax, ay);
    }
}

// ===========================================================================
// K3: logits = h @ lw^T via f16 HMMA (fp32 acc) + fused bias/log_softmax.
//     grid (KS, GT), block 256 (8 warps). Warp = 16 graphs x 16 cls x K256.
// ===========================================================================
__global__ __launch_bounds__(256) void k3_cls(const float* __restrict__ lb,
                                              float* __restrict__ out)
{
    __shared__ float red[8][256];
    __shared__ int flag;

    const int tid  = threadIdx.x;
    const int wid  = tid >> 5;
    const int lane = tid & 31;
    const int grp  = lane >> 2;     // 0..7
    const int t    = lane & 3;      // 0..3

    const int kb = blockIdx.x * 2048;     // block K chunk (halves)
    const int g0 = blockIdx.y * 16;

    const int kw = kb + wid * 256;        // warp K slice

    float d0[4] = {0.f, 0.f, 0.f, 0.f};   // classes 0-7
    float d1[4] = {0.f, 0.f, 0.f, 0.f};   // classes 8-15

    const __half* ha = g_h16 + (size_t)(g0 + grp) * NK;
    const __half* hb = g_h16 + (size_t)(g0 + 8 + grp) * NK;
    const __half* w0 = g_lwh + (size_t)(grp) * NK;
    const __half* w1 = g_lwh + (size_t)(8 + grp) * NK;

    #pragma unroll 4
    for (int s = 0; s < 16; s++) {
        const int k = kw + s * 16 + 2 * t;
        uint32_t a0 = *(const uint32_t*)&ha[k];
        uint32_t a1 = *(const uint32_t*)&hb[k];
        uint32_t a2 = *(const uint32_t*)&ha[k + 8];
        uint32_t a3 = *(const uint32_t*)&hb[k + 8];
        uint32_t b00 = *(const uint32_t*)&w0[k];
        uint32_t b01 = *(const uint32_t*)&w0[k + 8];
        uint32_t b10 = *(const uint32_t*)&w1[k];
        uint32_t b11 = *(const uint32_t*)&w1[k + 8];
        MMA_F16(d0, a0, a1, a2, a3, b00, b01);
        MMA_F16(d1, a0, a1, a2, a3, b10, b11);
    }

    // scatter warp's 16x16 tile into red[wid]
    {
        float* r = red[wid];
        r[(grp    ) * 16 + 2 * t    ] = d0[0];
        r[(grp    ) * 16 + 2 * t + 1] = d0[1];
        r[(grp + 8) * 16 + 2 * t    ] = d0[2];
        r[(grp + 8) * 16 + 2 * t + 1] = d0[3];
        r[(grp    ) * 16 + 2 * t + 8] = d1[0];
        r[(grp    ) * 16 + 2 * t + 9] = d1[1];
        r[(grp + 8) * 16 + 2 * t + 8] = d1[2];
        r[(grp + 8) * 16 + 2 * t + 9] = d1[3];
    }
    __syncthreads();

    // combine 8 warps -> atomic into g_logits (tid = g*16 + c)
    {
        float s = 0.f;
        #pragma unroll
        for (int w = 0; w < 8; w++) s += red[w][tid];
        atomicAdd(&g_logits[(size_t)g0 * Cc + tid], s);
    }

    // completion: last ksplit block for this gtile runs softmax
    __threadfence();
    __syncthreads();
    if (tid == 0)
        flag = (atomicAdd(&g_cnt[blockIdx.y], 1) == KS - 1) ? 1 : 0;
    __syncthreads();
    if (flag) {
        __threadfence();
        const int g = g0 + (tid >> 4);
        const int c = tid & 15;
        float s = g_logits[(size_t)g * Cc + c] + __ldg(&lb[c]);
        float m = s;
        #pragma unroll
        for (int o = 8; o > 0; o >>= 1)
            m = fmaxf(m, __shfl_xor_sync(0xffffffffu, m, o, 16));
        float se = expf(s - m);
        #pragma unroll
        for (int o = 8; o > 0; o >>= 1)
            se += __shfl_xor_sync(0xffffffffu, se, o, 16);
        out[(size_t)g * Cc + c] = (s - m) - logf(se);
    }
}

// ===========================================================================
extern "C" void kernel_launch(void* const* d_in, const int* in_sizes, int n_in,
                              void* d_out, int out_size)
{
    const float* x  = (const float*)d_in[0];   // [G, N, F_IN]
    const int*   ei = (const int*)  d_in[1];   // [G, 2, E]
    const float* cw = (const float*)d_in[2];   // [F_OUT, F_IN]
    const float* cb = (const float*)d_in[3];   // [F_OUT]
    const float* lw = (const float*)d_in[4];   // [C, N*F_OUT]
    const float* lb = (const float*)d_in[5];   // [C]
    float* out = (float*)d_out;                // [G, C]

    // do-once: keep attribute call out of the graph-capture pass
    static bool inited = false;
    if (!inited) {
        cudaFuncSetAttribute(kAB,
                             cudaFuncAttributeMaxDynamicSharedMemorySize,
                             KAB_SMEM);
        inited = true;
    }

    kAB   <<<Gg, 512, KAB_SMEM>>>(x, cw, ei, lw, cb);
    k3_cls<<<dim3(KS, GT), 256>>>(lb, out);
}